// round 15
// baseline (speedup 1.0000x reference)
#include <cuda_runtime.h>
#include <cuda_fp16.h>
#include <math.h>
#include <stdint.h>

#define BATCH 8
#define SEQ 1024
#define DIM 512
#define HEADS 16
#define HD 32
#define MROWS (BATCH*SEQ)   /* 8192 */
#define MLPH 2048
#define TBLN 3969           /* (2*32-1)^2 */

// ---------------- scratch (device globals; no allocations allowed) ----------
__device__ __align__(256) __half g_h[MROWS * DIM];         // LN out (fp16)
__device__ __align__(256) __half g_qkv[MROWS * 3 * DIM];   // q|k|v (fp16)
__device__ __align__(256) __half g_vt[BATCH * HEADS * HD * SEQ]; // V^T per (b,h)
__device__ __align__(256) __half g_attnout[MROWS * DIM];   // attention out (fp16)
__device__ __align__(256) __half g_mlp1[MROWS * MLPH];     // gelu(fc1) (fp16)
__device__ __align__(256) __half g_w[3145728];             // [N][K] fp16 weights
__device__ float g_xres[MROWS * DIM];                      // x + proj(attn) fp32
__device__ float g_tblt[HEADS * TBLN];                     // transposed bias table

#define W_QKV  0
#define W_PROJ 786432
#define W_FC1  1048576
#define W_FC2  2097152

// ---------------- helpers ----------------------------------------------------
__device__ __forceinline__ void mma_f16(float* c, uint32_t a0, uint32_t a1,
                                        uint32_t a2, uint32_t a3,
                                        uint32_t b0, uint32_t b1) {
    asm volatile(
        "mma.sync.aligned.m16n8k16.row.col.f32.f16.f16.f32 "
        "{%0,%1,%2,%3}, {%4,%5,%6,%7}, {%8,%9}, {%0,%1,%2,%3};"
        : "+f"(c[0]), "+f"(c[1]), "+f"(c[2]), "+f"(c[3])
        : "r"(a0), "r"(a1), "r"(a2), "r"(a3), "r"(b0), "r"(b1));
}

__device__ __forceinline__ void ldsm4(uint32_t& r0, uint32_t& r1,
                                      uint32_t& r2, uint32_t& r3, uint32_t addr) {
    asm volatile("ldmatrix.sync.aligned.m8n8.x4.shared.b16 {%0,%1,%2,%3}, [%4];"
                 : "=r"(r0), "=r"(r1), "=r"(r2), "=r"(r3) : "r"(addr));
}

__device__ __forceinline__ void cp16(uint32_t s, const void* g) {
    asm volatile("cp.async.cg.shared.global [%0], [%1], 16;\n" :: "r"(s), "l"(g));
}
__device__ __forceinline__ void cp_commit() {
    asm volatile("cp.async.commit_group;\n");
}
template <int N> __device__ __forceinline__ void cp_wait() {
    asm volatile("cp.async.wait_group %0;\n" :: "n"(N));
}
__device__ __forceinline__ uint32_t smem_u32(const void* p) {
    uint32_t a;
    asm("{ .reg .u64 t; cvta.to.shared.u64 t, %1; cvt.u32.u64 %0, t; }"
        : "=r"(a) : "l"(p));
    return a;
}
__device__ __forceinline__ uint32_t pack_h2(float lo, float hi) {
    const __half2 h = __floats2half2_rn(lo, hi);
    return *(const uint32_t*)&h;
}

// ---------------- merged weight transpose + fp16 convert ---------------------
__global__ void __launch_bounds__(256) cvt_all_kernel(const float* __restrict__ qkv_w,
                                                      const float* __restrict__ proj_w,
                                                      const float* __restrict__ fc1_w,
                                                      const float* __restrict__ fc2_w,
                                                      __half* __restrict__ w)
{
    __shared__ float tile[32][33];
    const int bid = blockIdx.x;
    const float* in;
    __half* out;
    int K, N, tid2;
    if (bid < 768)       { in = qkv_w;  out = w + W_QKV;  K = DIM;  N = 3 * DIM; tid2 = bid; }
    else if (bid < 1024) { in = proj_w; out = w + W_PROJ; K = DIM;  N = DIM;     tid2 = bid - 768; }
    else if (bid < 2048) { in = fc1_w;  out = w + W_FC1;  K = DIM;  N = MLPH;    tid2 = bid - 1024; }
    else                 { in = fc2_w;  out = w + W_FC2;  K = MLPH; N = DIM;     tid2 = bid - 2048; }
    const int ntx = N >> 5;
    const int bn = (tid2 % ntx) * 32, bk = (tid2 / ntx) * 32;
    const int tx = threadIdx.x, ty = threadIdx.y;
    #pragma unroll
    for (int i = 0; i < 4; i++)
        tile[ty + 8 * i][tx] = in[(size_t)(bk + ty + 8 * i) * N + bn + tx];
    __syncthreads();
    #pragma unroll
    for (int i = 0; i < 4; i++) {
        const int n = ty + 8 * i;
        out[(size_t)(bn + n) * K + bk + tx] = __float2half_rn(tile[tx][n]);
    }
}

// ---------------- bias-table transpose ---------------------------------------
__global__ void __launch_bounds__(256) tblt_kernel(const float* __restrict__ table)
{
    const int i = blockIdx.x * 256 + threadIdx.x;
    if (i < TBLN) {
        #pragma unroll
        for (int h = 0; h < HEADS; h++)
            g_tblt[h * TBLN + i] = table[i * HEADS + h];
    }
}

// ---------------- V transpose ------------------------------------------------
__global__ void __launch_bounds__(256) vt_kernel()
{
    __shared__ __half tile[32][34];
    const int m0 = blockIdx.x * 32, h = blockIdx.y, b = blockIdx.z;
    const int tx = threadIdx.x, ty = threadIdx.y;
    const __half* in = g_qkv + (size_t)(b * SEQ) * (3 * DIM) + 2 * DIM + h * HD;
    #pragma unroll
    for (int i = 0; i < 4; i++)
        tile[ty + 8 * i][tx] = in[(size_t)(m0 + ty + 8 * i) * (3 * DIM) + tx];
    __syncthreads();
    __half* out = g_vt + ((size_t)(b * HEADS + h) * HD) * SEQ + m0;
    #pragma unroll
    for (int i = 0; i < 4; i++) {
        const int d = ty + 8 * i;
        out[(size_t)d * SEQ + tx] = tile[tx][d];
    }
}

// ---------------- LayerNorm (fp16 output) ------------------------------------
__global__ void __launch_bounds__(128) ln_kernel(const float* __restrict__ x,
                                                 const float* __restrict__ g,
                                                 const float* __restrict__ b,
                                                 __half* __restrict__ out)
{
    const int row = blockIdx.x;
    const int t = threadIdx.x;
    const float4 v = ((const float4*)(x + (size_t)row * DIM))[t];
    float s  = v.x + v.y + v.z + v.w;
    float s2 = v.x*v.x + v.y*v.y + v.z*v.z + v.w*v.w;
    #pragma unroll
    for (int o = 16; o > 0; o >>= 1) {
        s  += __shfl_xor_sync(0xffffffffu, s,  o);
        s2 += __shfl_xor_sync(0xffffffffu, s2, o);
    }
    __shared__ float rs[4], rs2[4];
    if ((t & 31) == 0) { rs[t >> 5] = s; rs2[t >> 5] = s2; }
    __syncthreads();
    s  = rs[0] + rs[1] + rs[2] + rs[3];
    s2 = rs2[0] + rs2[1] + rs2[2] + rs2[3];
    const float mean = s * (1.0f / DIM);
    const float var  = s2 * (1.0f / DIM) - mean * mean;
    const float inv  = rsqrtf(var + 1e-5f);
    const float4 gg = ((const float4*)g)[t];
    const float4 bb = ((const float4*)b)[t];
    __half2* op = (__half2*)(out + (size_t)row * DIM + 4 * t);
    op[0] = __floats2half2_rn((v.x - mean) * inv * gg.x + bb.x,
                              (v.y - mean) * inv * gg.y + bb.y);
    op[1] = __floats2half2_rn((v.z - mean) * inv * gg.z + bb.z,
                              (v.w - mean) * inv * gg.w + bb.w);
}

// ---------------- fp16 GEMM: 8 warps (4x2), 32x64 warp tile, ldmatrix --------
// C[M,N] = epilogue(A[M,K] @ Wt[N,K]^T + bias [, R])
// 128x128 block, BK=32, 256 thr, 3-stage cp.async, m16n8k16.
enum { EPI_BIAS = 0, EPI_GELU = 1, EPI_RES = 2 };

template <int EPI, int OUTH>
__global__ void __launch_bounds__(256, 2) gemm_h(const __half* __restrict__ A,
                                                 const __half* __restrict__ Wt,
                                                 const float* __restrict__ bias,
                                                 const float* __restrict__ R,
                                                 float* __restrict__ Cf,
                                                 __half* __restrict__ Ch,
                                                 int M, int N, int K)
{
    __shared__ __align__(16) __half As[3][128][40];   // [m][k]
    __shared__ __align__(16) __half Bs[3][128][40];   // [n][k]

    const int bm = blockIdx.y * 128, bn = blockIdx.x * 128;
    const int tid = threadIdx.x;
    const int warp = tid >> 5, lane = tid & 31;
    const int wm = (warp & 3) * 32, wn = (warp >> 2) * 64;
    const int g = lane >> 2, t4 = lane & 3;

    // staging: 512 16B-chunks per operand, 2 per thread
    const int srow = tid >> 2, sch = (tid & 3) * 8;

    // ldmatrix per-lane offsets (halfs; row stride 40)
    const int a_off = (wm + (lane & 15)) * 40 + (lane >> 4) * 8;
    const int b_off = (wn + (lane & 7) + ((lane >> 4) & 1) * 8) * 40
                      + ((lane >> 3) & 1) * 8;

    float acc[2][8][4];
    #pragma unroll
    for (int mi = 0; mi < 2; mi++)
        #pragma unroll
        for (int ni = 0; ni < 8; ni++)
            #pragma unroll
            for (int c = 0; c < 4; c++) acc[mi][ni][c] = 0.0f;

    const int nk = K >> 5;

    #pragma unroll
    for (int st = 0; st < 2; st++) {
        const int k0 = st * 32;
        #pragma unroll
        for (int i = 0; i < 2; i++) {
            const int r = srow + i * 64;
            cp16(smem_u32(&As[st][r][sch]), A + (size_t)(bm + r) * K + k0 + sch);
            cp16(smem_u32(&Bs[st][r][sch]), Wt + (size_t)(bn + r) * K + k0 + sch);
        }
        cp_commit();
    }

    int s = 0;
    for (int kt = 0; kt < nk; kt++) {
        if (kt + 2 < nk) {
            const int k0 = (kt + 2) * 32;
            const int sn = (s + 2) % 3;
            #pragma unroll
            for (int i = 0; i < 2; i++) {
                const int r = srow + i * 64;
                cp16(smem_u32(&As[sn][r][sch]), A + (size_t)(bm + r) * K + k0 + sch);
                cp16(smem_u32(&Bs[sn][r][sch]), Wt + (size_t)(bn + r) * K + k0 + sch);
            }
            cp_commit();
            cp_wait<2>();
        } else if (kt + 1 < nk) {
            cp_wait<1>();
        } else {
            cp_wait<0>();
        }
        __syncthreads();

        const uint32_t asb = smem_u32(&As[s][0][0]);
        const uint32_t bsb = smem_u32(&Bs[s][0][0]);

        #pragma unroll
        for (int ks = 0; ks < 2; ks++) {
            uint32_t a[2][4], bb[8][2];
            #pragma unroll
            for (int mi = 0; mi < 2; mi++)
                ldsm4(a[mi][0], a[mi][1], a[mi][2], a[mi][3],
                      asb + (uint32_t)(a_off + mi * 16 * 40 + ks * 16) * 2);
            #pragma unroll
            for (int nj = 0; nj < 4; nj++)
                ldsm4(bb[2 * nj][0], bb[2 * nj][1], bb[2 * nj + 1][0], bb[2 * nj + 1][1],
                      bsb + (uint32_t)(b_off + nj * 16 * 40 + ks * 16) * 2);
            #pragma unroll
            for (int ni = 0; ni < 8; ni++)
                #pragma unroll
                for (int mi = 0; mi < 2; mi++)
                    mma_f16(acc[mi][ni], a[mi][0], a[mi][1], a[mi][2], a[mi][3],
                            bb[ni][0], bb[ni][1]);
        }
        __syncthreads();
        s = (s + 1) % 3;
    }

    #pragma unroll
    for (int mi = 0; mi < 2; mi++) {
        const int r0 = bm + wm + mi * 16 + g;
        #pragma unroll
        for (int ni = 0; ni < 8; ni++) {
            const int col = bn + wn + ni * 8 + t4 * 2;
            const float b0 = bias[col], b1 = bias[col + 1];
            float v[4];
            v[0] = acc[mi][ni][0] + b0;
            v[1] = acc[mi][ni][1] + b1;
            v[2] = acc[mi][ni][2] + b0;
            v[3] = acc[mi][ni][3] + b1;
            if (EPI == EPI_GELU) {
                #pragma unroll
                for (int c = 0; c < 4; c++)
                    v[c] = 0.5f * v[c] * (1.0f + erff(v[c] * 0.70710678118654752f));
            }
            if (EPI == EPI_RES) {
                const float2 r4a = *(const float2*)(R + (size_t)r0 * N + col);
                const float2 r4b = *(const float2*)(R + (size_t)(r0 + 8) * N + col);
                v[0] += r4a.x; v[1] += r4a.y;
                v[2] += r4b.x; v[3] += r4b.y;
            }
            if (OUTH) {
                *(__half2*)(Ch + (size_t)r0 * N + col)       = __floats2half2_rn(v[0], v[1]);
                *(__half2*)(Ch + (size_t)(r0 + 8) * N + col) = __floats2half2_rn(v[2], v[3]);
            } else {
                *(float2*)(Cf + (size_t)r0 * N + col)       = make_float2(v[0], v[1]);
                *(float2*)(Cf + (size_t)(r0 + 8) * N + col) = make_float2(v[2], v[3]);
            }
        }
    }
}

// ---------------- Flash attention: ldmatrix frags, 64-q blocks, 4/SM ---------
#define NIT (SEQ / 64)

__global__ void __launch_bounds__(128, 4) attn_h_kernel(__half* __restrict__ out)
{
    __shared__ __align__(16) __half Ks[3][64][40];   // [key][d]
    __shared__ __align__(16) __half Vt[3][32][72];   // [d][key]
    __shared__ float tbl[TBLN];

    const int b = blockIdx.z, h = blockIdx.y, q0 = blockIdx.x * 64;
    const int tid = threadIdx.x;
    const int warp = tid >> 5, lane = tid & 31;
    const int g = lane >> 2, t4 = lane & 3;
    const int wq = warp * 16;

    const float scale = 0.17677669529663687f;  // 1/sqrt(32)

    const int kkey = tid >> 2, kch = (tid & 3) * 8;
    const int vd = tid >> 3, vch = (tid & 7) * 8;

    const __half* kbase = g_qkv + (size_t)(b * SEQ + kkey) * (3 * DIM)
                          + DIM + h * HD + kch;
    const __half* vbase = g_vt + ((size_t)(b * HEADS + h) * HD + vd) * SEQ + vch;
    const size_t kstep = (size_t)32 * (3 * DIM);
    const size_t vstep = (size_t)16 * SEQ;

    const int kb_off = ((lane & 7) + ((lane >> 4) & 1) * 8) * 40
                       + ((lane >> 3) & 1) * 8;
    const int vb_off = ((lane & 7) + ((lane >> 4) & 1) * 8) * 72
                       + ((lane >> 3) & 1) * 8;

    #pragma unroll
    for (int st = 0; st < 2; st++) {
        cp16(smem_u32(&Ks[st][kkey][kch]), kbase + (size_t)(st * 64) * (3 * DIM));
        cp16(smem_u32(&Ks[st][kkey + 32][kch]),
             kbase + (size_t)(st * 64) * (3 * DIM) + kstep);
        cp16(smem_u32(&Vt[st][vd][vch]), vbase + st * 64);
        cp16(smem_u32(&Vt[st][vd + 16][vch]), vbase + st * 64 + vstep);
        cp_commit();
    }

    {
        const float* tsrc = g_tblt + (size_t)h * TBLN;
        for (int i = tid; i < TBLN; i += 128) tbl[i] = tsrc[i];
    }

    uint32_t qf[2][4];
    {
        const __half* q0p = g_qkv + (size_t)(b * SEQ + q0 + wq + g) * (3 * DIM) + h * HD;
        const __half* q1p = q0p + 8 * (3 * DIM);
        #pragma unroll
        for (int ks = 0; ks < 2; ks++) {
            const int kc = 16 * ks + 2 * t4;
            qf[ks][0] = *(const uint32_t*)(q0p + kc);
            qf[ks][1] = *(const uint32_t*)(q1p + kc);
            qf[ks][2] = *(const uint32_t*)(q0p + kc + 8);
            qf[ks][3] = *(const uint32_t*)(q1p + kc + 8);
        }
    }

    const int l0 = q0 + wq + g, l1 = l0 + 8;
    const int Cb0 = (l0 >> 5) * 63 + (l0 & 31) + 1984;
    const int Cb1 = (l1 >> 5) * 63 + (l1 & 31) + 1984;

    float m0 = -1e30f, m1 = -1e30f, li0 = 0.0f, li1 = 0.0f;
    float acc_o[4][4];
    #pragma unroll
    for (int ni = 0; ni < 4; ni++)
        #pragma unroll
        for (int c = 0; c < 4; c++) acc_o[ni][c] = 0.0f;

    for (int it = 0; it < NIT; it++) {
        const int s = it % 3;
        if (it + 1 < NIT) cp_wait<1>(); else cp_wait<0>();
        __syncthreads();
        if (it + 2 < NIT) {
            const int sn = (it + 2) % 3;
            const size_t ko = (size_t)((it + 2) * 64) * (3 * DIM);
            cp16(smem_u32(&Ks[sn][kkey][kch]), kbase + ko);
            cp16(smem_u32(&Ks[sn][kkey + 32][kch]), kbase + ko + kstep);
            cp16(smem_u32(&Vt[sn][vd][vch]), vbase + (it + 2) * 64);
            cp16(smem_u32(&Vt[sn][vd + 16][vch]), vbase + (it + 2) * 64 + vstep);
            cp_commit();
        }

        const uint32_t ksb = smem_u32(&Ks[s][0][0]);
        const uint32_t vsb = smem_u32(&Vt[s][0][0]);

        float sacc[8][4];
        #pragma unroll
        for (int ni = 0; ni < 8; ni++)
            #pragma unroll
            for (int c = 0; c < 4; c++) sacc[ni][c] = 0.0f;
        #pragma unroll
        for (int ks = 0; ks < 2; ks++) {
            uint32_t kb[8][2];
            #pragma unroll
            for (int nj = 0; nj < 4; nj++)
                ldsm4(kb[2 * nj][0], kb[2 * nj][1], kb[2 * nj + 1][0], kb[2 * nj + 1][1],
                      ksb + (uint32_t)(kb_off + nj * 16 * 40 + ks * 16) * 2);
            #pragma unroll
            for (int ni = 0; ni < 8; ni++)
                mma_f16(sacc[ni], qf[ks][0], qf[ks][1], qf[ks][2], qf[ks][3],
                        kb[ni][0], kb[ni][1]);
        }
        const int k0 = it * 64;
        {
            const int base0 = Cb0 - (k0 >> 5) * 63;
            const int base1 = Cb1 - (k0 >> 5) * 63;
            #pragma unroll
            for (int ni = 0; ni < 8; ni++) {
                const int off = (ni >> 2) * 63 + 8 * (ni & 3) + 2 * t4;
                sacc[ni][0] = fmaf(sacc[ni][0], scale, tbl[base0 - off]);
                sacc[ni][1] = fmaf(sacc[ni][1], scale, tbl[base0 - off - 1]);
                sacc[ni][2] = fmaf(sacc[ni][2], scale, tbl[base1 - off]);
                sacc[ni][3] = fmaf(sacc[ni][3], scale, tbl[base1 - off - 1]);
            }
        }

        float vmax0 = -1e30f, vmax1 = -1e30f;
        #pragma unroll
        for (int ni = 0; ni < 8; ni++) {
            vmax0 = fmaxf(vmax0, fmaxf(sacc[ni][0], sacc[ni][1]));
            vmax1 = fmaxf(vmax1, fmaxf(sacc[ni][2], sacc[ni][3]));
        }
        #pragma unroll
        for (int o = 1; o <= 2; o <<= 1) {
            vmax0 = fmaxf(vmax0, __shfl_xor_sync(0xffffffffu, vmax0, o));
            vmax1 = fmaxf(vmax1, __shfl_xor_sync(0xffffffffu, vmax1, o));
        }
        const float nm0 = fmaxf(m0, vmax0);
        const float nm1 = fmaxf(m1, vmax1);
        const float corr0 = __expf(m0 - nm0);
        const float corr1 = __expf(m1 - nm1);
        m0 = nm0; m1 = nm1;
        float rs0 = 0.0f, rs1 = 0.0f;

        uint32_t ph2[8][2];
        #pragma unroll
        for (int ni = 0; ni < 8; ni++) {
            const float p0 = __expf(sacc[ni][0] - m0);
            const float p1 = __expf(sacc[ni][1] - m0);
            const float p2 = __expf(sacc[ni][2] - m1);
            const float p3 = __expf(sacc[ni][3] - m1);
            rs0 += p0 + p1; rs1 += p2 + p3;
            ph2[ni][0] = pack_h2(p0, p1);
            ph2[ni][1] = pack_h2(p2, p3);
        }
        li0 = li0 * corr0 + rs0;
        li1 = li1 * corr1 + rs1;
        #pragma unroll
        for (int ni = 0; ni < 4; ni++) {
            acc_o[ni][0] *= corr0; acc_o[ni][1] *= corr0;
            acc_o[ni][2] *= corr1; acc_o[ni][3] *= corr1;
        }

        #pragma unroll
        for (int ks = 0; ks < 4; ks++) {
            uint32_t vb[4][2];
            #pragma unroll
            for (int nj = 0; nj < 2; nj++)
                ldsm4(vb[2 * nj][0], vb[2 * nj][1], vb[2 * nj + 1][0], vb[2 * nj + 1][1],
                      vsb + (uint32_t)(vb_off + nj * 16 * 72 + ks * 16) * 2);
            const uint32_t a0 = ph2[2 * ks][0];
            const uint32_t a1 = ph2[2 * ks][1];
            const uint32_t a2 = ph2[2 * ks + 1][0];
            const uint32_t a3 = ph2[2 * ks + 1][1];
            #pragma unroll
            for (int ni = 0; ni < 4; ni++)
                mma_f16(acc_o[ni], a0, a1, a2, a3, vb[ni][0], vb[ni][1]);
        }
    }

    #pragma unroll
    for (int o = 1; o <= 2; o <<= 1) {
        li0 += __shfl_xor_sync(0xffffffffu, li0, o);
        li1 += __shfl_xor_sync(0xffffffffu, li1, o);
    }
    const float inv0 = 1.0f / li0;
    const float inv1 = 1.0f / li1;
    __half* o0p = out + (size_t)(b * SEQ + q0 + wq + g) * DIM + h * HD;
    __half* o1p = o0p + 8 * DIM;
    #pragma unroll
    for (int ni = 0; ni < 4; ni++) {
        const int col = ni * 8 + t4 * 2;
        *(__half2*)(o0p + col) = __floats2half2_rn(acc_o[ni][0] * inv0,
                                                   acc_o[ni][1] * inv0);
        *(__half2*)(o1p + col) = __floats2half2_rn(acc_o[ni][2] * inv1,
                                                   acc_o[ni][3] * inv1);
    }
}

// ---------------- launch -----------------------------------------------------
extern "C" void kernel_launch(void* const* d_in, const int* in_sizes, int n_in,
                              void* d_out, int out_size)
{
    const float* x      = (const float*)d_in[0];
    const float* table  = (const float*)d_in[2];
    const float* qkv_w  = (const float*)d_in[3];
    const float* qkv_b  = (const float*)d_in[4];
    const float* proj_w = (const float*)d_in[5];
    const float* proj_b = (const float*)d_in[6];
    const float* n1_g   = (const float*)d_in[7];
    const float* n1_b   = (const float*)d_in[8];
    const float* n2_g   = (const float*)d_in[9];
    const float* n2_b   = (const float*)d_in[10];
    const float* fc1_w  = (const float*)d_in[11];
    const float* fc1_b  = (const float*)d_in[12];
    const float* fc2_w  = (const float*)d_in[13];
    const float* fc2_b  = (const float*)d_in[14];
    float* out = (float*)d_out;

    __half *h, *qkv, *attnout, *mlp1, *w;
    float *xres;
    cudaGetSymbolAddress((void**)&h,       g_h);
    cudaGetSymbolAddress((void**)&qkv,     g_qkv);
    cudaGetSymbolAddress((void**)&attnout, g_attnout);
    cudaGetSymbolAddress((void**)&xres,    g_xres);
    cudaGetSymbolAddress((void**)&mlp1,    g_mlp1);
    cudaGetSymbolAddress((void**)&w,       g_w);

    dim3 tb(32, 8);
    cvt_all_kernel<<<3072, tb>>>(qkv_w, proj_w, fc1_w, fc2_w, w);
    tblt_kernel<<<(TBLN + 255) / 256, 256>>>(table);
    ln_kernel<<<MROWS, 128>>>(x, n1_g, n1_b, h);
    gemm_h<EPI_BIAS, 1><<<dim3(12, 64), 256>>>(h, w + W_QKV, qkv_b, nullptr,
                                               nullptr, qkv, MROWS, 3 * DIM, DIM);
    vt_kernel<<<dim3(SEQ / 32, HEADS, BATCH), tb>>>();
    attn_h_kernel<<<dim3(SEQ / 64, HEADS, BATCH), 128>>>(attnout);
    gemm_h<EPI_RES, 0><<<dim3(4, 64), 256>>>(attnout, w + W_PROJ, proj_b, x,
                                             xres, nullptr, MROWS, DIM, DIM);
    ln_kernel<<<MROWS, 128>>>(xres, n2_g, n2_b, h);
    gemm_h<EPI_GELU, 1><<<dim3(16, 64), 256>>>(h, w + W_FC1, fc1_b, nullptr,
                                               nullptr, mlp1, MROWS, MLPH, DIM);
    gemm_h<EPI_RES, 0><<<dim3(4, 64), 256>>>(mlp1, w + W_FC2, fc2_b, xres,
                                             out, nullptr, MROWS, DIM, MLPH);
}

// round 17
// speedup vs baseline: 1.0440x; 1.0440x over previous
#include <cuda_runtime.h>
#include <cuda_fp16.h>
#include <math.h>
#include <stdint.h>

#define BATCH 8
#define SEQ 1024
#define DIM 512
#define HEADS 16
#define HD 32
#define MROWS (BATCH*SEQ)   /* 8192 */
#define MLPH 2048
#define TBLN 3969           /* (2*32-1)^2 */

// ---------------- scratch (device globals; no allocations allowed) ----------
__device__ __align__(256) __half g_h[MROWS * DIM];         // LN out (fp16)
__device__ __align__(256) __half g_qkv[MROWS * 3 * DIM];   // q|k|v (fp16)
__device__ __align__(256) __half g_vt[BATCH * HEADS * HD * SEQ]; // V^T per (b,h)
__device__ __align__(256) __half g_attnout[MROWS * DIM];   // attention out (fp16)
__device__ __align__(256) __half g_mlp1[MROWS * MLPH];     // gelu(fc1) (fp16)
__device__ __align__(256) __half g_w[3145728];             // [N][K] fp16 weights
__device__ float g_xres[MROWS * DIM];                      // x + proj(attn) fp32
__device__ float g_tblt[HEADS * TBLN];                     // transposed bias table

#define W_QKV  0
#define W_PROJ 786432
#define W_FC1  1048576
#define W_FC2  2097152

// ---------------- helpers ----------------------------------------------------
__device__ __forceinline__ void mma_f16(float* c, uint32_t a0, uint32_t a1,
                                        uint32_t a2, uint32_t a3,
                                        uint32_t b0, uint32_t b1) {
    asm volatile(
        "mma.sync.aligned.m16n8k16.row.col.f32.f16.f16.f32 "
        "{%0,%1,%2,%3}, {%4,%5,%6,%7}, {%8,%9}, {%0,%1,%2,%3};"
        : "+f"(c[0]), "+f"(c[1]), "+f"(c[2]), "+f"(c[3])
        : "r"(a0), "r"(a1), "r"(a2), "r"(a3), "r"(b0), "r"(b1));
}

__device__ __forceinline__ void ldsm4(uint32_t& r0, uint32_t& r1,
                                      uint32_t& r2, uint32_t& r3, uint32_t addr) {
    asm volatile("ldmatrix.sync.aligned.m8n8.x4.shared.b16 {%0,%1,%2,%3}, [%4];"
                 : "=r"(r0), "=r"(r1), "=r"(r2), "=r"(r3) : "r"(addr));
}

__device__ __forceinline__ void cp16(uint32_t s, const void* g) {
    asm volatile("cp.async.cg.shared.global [%0], [%1], 16;\n" :: "r"(s), "l"(g));
}
__device__ __forceinline__ void cp_commit() {
    asm volatile("cp.async.commit_group;\n");
}
template <int N> __device__ __forceinline__ void cp_wait() {
    asm volatile("cp.async.wait_group %0;\n" :: "n"(N));
}
__device__ __forceinline__ uint32_t smem_u32(const void* p) {
    uint32_t a;
    asm("{ .reg .u64 t; cvta.to.shared.u64 t, %1; cvt.u32.u64 %0, t; }"
        : "=r"(a) : "l"(p));
    return a;
}
__device__ __forceinline__ uint32_t pack_h2(float lo, float hi) {
    const __half2 h = __floats2half2_rn(lo, hi);
    return *(const uint32_t*)&h;
}

// ---------------- merged weight transpose + fp16 convert ---------------------
__global__ void __launch_bounds__(256) cvt_all_kernel(const float* __restrict__ qkv_w,
                                                      const float* __restrict__ proj_w,
                                                      const float* __restrict__ fc1_w,
                                                      const float* __restrict__ fc2_w,
                                                      __half* __restrict__ w)
{
    __shared__ float tile[32][33];
    const int bid = blockIdx.x;
    const float* in;
    __half* out;
    int K, N, tid2;
    if (bid < 768)       { in = qkv_w;  out = w + W_QKV;  K = DIM;  N = 3 * DIM; tid2 = bid; }
    else if (bid < 1024) { in = proj_w; out = w + W_PROJ; K = DIM;  N = DIM;     tid2 = bid - 768; }
    else if (bid < 2048) { in = fc1_w;  out = w + W_FC1;  K = DIM;  N = MLPH;    tid2 = bid - 1024; }
    else                 { in = fc2_w;  out = w + W_FC2;  K = MLPH; N = DIM;     tid2 = bid - 2048; }
    const int ntx = N >> 5;
    const int bn = (tid2 % ntx) * 32, bk = (tid2 / ntx) * 32;
    const int tx = threadIdx.x, ty = threadIdx.y;
    #pragma unroll
    for (int i = 0; i < 4; i++)
        tile[ty + 8 * i][tx] = in[(size_t)(bk + ty + 8 * i) * N + bn + tx];
    __syncthreads();
    #pragma unroll
    for (int i = 0; i < 4; i++) {
        const int n = ty + 8 * i;
        out[(size_t)(bn + n) * K + bk + tx] = __float2half_rn(tile[tx][n]);
    }
}

// ---------------- bias-table transpose ---------------------------------------
__global__ void __launch_bounds__(256) tblt_kernel(const float* __restrict__ table)
{
    const int i = blockIdx.x * 256 + threadIdx.x;
    if (i < TBLN) {
        #pragma unroll
        for (int h = 0; h < HEADS; h++)
            g_tblt[h * TBLN + i] = table[i * HEADS + h];
    }
}

// ---------------- V transpose ------------------------------------------------
__global__ void __launch_bounds__(256) vt_kernel()
{
    __shared__ __half tile[32][34];
    const int m0 = blockIdx.x * 32, h = blockIdx.y, b = blockIdx.z;
    const int tx = threadIdx.x, ty = threadIdx.y;
    const __half* in = g_qkv + (size_t)(b * SEQ) * (3 * DIM) + 2 * DIM + h * HD;
    #pragma unroll
    for (int i = 0; i < 4; i++)
        tile[ty + 8 * i][tx] = in[(size_t)(m0 + ty + 8 * i) * (3 * DIM) + tx];
    __syncthreads();
    __half* out = g_vt + ((size_t)(b * HEADS + h) * HD) * SEQ + m0;
    #pragma unroll
    for (int i = 0; i < 4; i++) {
        const int d = ty + 8 * i;
        out[(size_t)d * SEQ + tx] = tile[tx][d];
    }
}

// ---------------- LayerNorm (fp16 output) ------------------------------------
__global__ void __launch_bounds__(128) ln_kernel(const float* __restrict__ x,
                                                 const float* __restrict__ g,
                                                 const float* __restrict__ b,
                                                 __half* __restrict__ out)
{
    const int row = blockIdx.x;
    const int t = threadIdx.x;
    const float4 v = ((const float4*)(x + (size_t)row * DIM))[t];
    float s  = v.x + v.y + v.z + v.w;
    float s2 = v.x*v.x + v.y*v.y + v.z*v.z + v.w*v.w;
    #pragma unroll
    for (int o = 16; o > 0; o >>= 1) {
        s  += __shfl_xor_sync(0xffffffffu, s,  o);
        s2 += __shfl_xor_sync(0xffffffffu, s2, o);
    }
    __shared__ float rs[4], rs2[4];
    if ((t & 31) == 0) { rs[t >> 5] = s; rs2[t >> 5] = s2; }
    __syncthreads();
    s  = rs[0] + rs[1] + rs[2] + rs[3];
    s2 = rs2[0] + rs2[1] + rs2[2] + rs2[3];
    const float mean = s * (1.0f / DIM);
    const float var  = s2 * (1.0f / DIM) - mean * mean;
    const float inv  = rsqrtf(var + 1e-5f);
    const float4 gg = ((const float4*)g)[t];
    const float4 bb = ((const float4*)b)[t];
    __half2* op = (__half2*)(out + (size_t)row * DIM + 4 * t);
    op[0] = __floats2half2_rn((v.x - mean) * inv * gg.x + bb.x,
                              (v.y - mean) * inv * gg.y + bb.y);
    op[1] = __floats2half2_rn((v.z - mean) * inv * gg.z + bb.z,
                              (v.w - mean) * inv * gg.w + bb.w);
}

// ---------------- fp16 GEMM: 4 warps (2x2) 64x64 tiles, BK=64, ldmatrix ------
// C[M,N] = epilogue(A[M,K] @ Wt[N,K]^T + bias [, R])
// 128x128 block, BK=64, 128 thr, 2-stage cp.async, m16n8k16.
enum { EPI_BIAS = 0, EPI_GELU = 1, EPI_RES = 2 };

template <int EPI, int OUTH>
__global__ void __launch_bounds__(128, 2) gemm_h(const __half* __restrict__ A,
                                                 const __half* __restrict__ Wt,
                                                 const float* __restrict__ bias,
                                                 const float* __restrict__ R,
                                                 float* __restrict__ Cf,
                                                 __half* __restrict__ Ch,
                                                 int M, int N, int K)
{
    __shared__ __align__(16) __half As[2][128][72];   // [m][k]
    __shared__ __align__(16) __half Bs[2][128][72];   // [n][k]

    const int bm = blockIdx.y * 128, bn = blockIdx.x * 128;
    const int tid = threadIdx.x;
    const int warp = tid >> 5, lane = tid & 31;
    const int wm = (warp & 1) * 64, wn = (warp >> 1) * 64;
    const int g = lane >> 2, t4 = lane & 3;

    // staging: 128 rows x 8 chunks(16B) per operand = 1024 chunks, 8/thread
    const int srow = tid >> 3 /* base row for fid=tid */, sch0 = (tid & 7) * 8;

    // ldmatrix per-lane offsets (halfs; row stride 72)
    const int a_off = (wm + (lane & 15)) * 72 + (lane >> 4) * 8;
    const int b_off = (wn + (lane & 7) + ((lane >> 4) & 1) * 8) * 72
                      + ((lane >> 3) & 1) * 8;

    float acc[4][8][4];
    #pragma unroll
    for (int mi = 0; mi < 4; mi++)
        #pragma unroll
        for (int ni = 0; ni < 8; ni++)
            #pragma unroll
            for (int c = 0; c < 4; c++) acc[mi][ni][c] = 0.0f;

    const int nk = K >> 6;

    // prologue: stage 0
    #pragma unroll
    for (int i = 0; i < 8; i++) {
        const int r = srow + i * 16;
        cp16(smem_u32(&As[0][r][sch0]), A + (size_t)(bm + r) * K + sch0);
        cp16(smem_u32(&Bs[0][r][sch0]), Wt + (size_t)(bn + r) * K + sch0);
    }
    cp_commit();

    for (int kt = 0; kt < nk; kt++) {
        const int s = kt & 1;
        if (kt + 1 < nk) {
            const int k0 = (kt + 1) * 64, sn = s ^ 1;
            #pragma unroll
            for (int i = 0; i < 8; i++) {
                const int r = srow + i * 16;
                cp16(smem_u32(&As[sn][r][sch0]), A + (size_t)(bm + r) * K + k0 + sch0);
                cp16(smem_u32(&Bs[sn][r][sch0]), Wt + (size_t)(bn + r) * K + k0 + sch0);
            }
            cp_commit();
            cp_wait<1>();
        } else {
            cp_wait<0>();
        }
        __syncthreads();

        const uint32_t asb = smem_u32(&As[s][0][0]);
        const uint32_t bsb = smem_u32(&Bs[s][0][0]);

        #pragma unroll
        for (int ks = 0; ks < 4; ks++) {
            uint32_t a[4][4], bb[8][2];
            #pragma unroll
            for (int mi = 0; mi < 4; mi++)
                ldsm4(a[mi][0], a[mi][1], a[mi][2], a[mi][3],
                      asb + (uint32_t)(a_off + mi * 16 * 72 + ks * 16) * 2);
            #pragma unroll
            for (int nj = 0; nj < 4; nj++)
                ldsm4(bb[2 * nj][0], bb[2 * nj][1], bb[2 * nj + 1][0], bb[2 * nj + 1][1],
                      bsb + (uint32_t)(b_off + nj * 16 * 72 + ks * 16) * 2);
            #pragma unroll
            for (int ni = 0; ni < 8; ni++)
                #pragma unroll
                for (int mi = 0; mi < 4; mi++)
                    mma_f16(acc[mi][ni], a[mi][0], a[mi][1], a[mi][2], a[mi][3],
                            bb[ni][0], bb[ni][1]);
        }
        __syncthreads();
    }

    #pragma unroll
    for (int mi = 0; mi < 4; mi++) {
        const int r0 = bm + wm + mi * 16 + g;
        #pragma unroll
        for (int ni = 0; ni < 8; ni++) {
            const int col = bn + wn + ni * 8 + t4 * 2;
            const float b0 = bias[col], b1 = bias[col + 1];
            float v[4];
            v[0] = acc[mi][ni][0] + b0;
            v[1] = acc[mi][ni][1] + b1;
            v[2] = acc[mi][ni][2] + b0;
            v[3] = acc[mi][ni][3] + b1;
            if (EPI == EPI_GELU) {
                #pragma unroll
                for (int c = 0; c < 4; c++)
                    v[c] = 0.5f * v[c] * (1.0f + erff(v[c] * 0.70710678118654752f));
            }
            if (EPI == EPI_RES) {
                const float2 r4a = *(const float2*)(R + (size_t)r0 * N + col);
                const float2 r4b = *(const float2*)(R + (size_t)(r0 + 8) * N + col);
                v[0] += r4a.x; v[1] += r4a.y;
                v[2] += r4b.x; v[3] += r4b.y;
            }
            if (OUTH) {
                *(__half2*)(Ch + (size_t)r0 * N + col)       = __floats2half2_rn(v[0], v[1]);
                *(__half2*)(Ch + (size_t)(r0 + 8) * N + col) = __floats2half2_rn(v[2], v[3]);
            } else {
                *(float2*)(Cf + (size_t)r0 * N + col)       = make_float2(v[0], v[1]);
                *(float2*)(Cf + (size_t)(r0 + 8) * N + col) = make_float2(v[2], v[3]);
            }
        }
    }
}

// ---------------- Flash attention: ldmatrix frags, 64-q blocks, 4/SM ---------
#define NIT (SEQ / 64)

__global__ void __launch_bounds__(128, 4) attn_h_kernel(__half* __restrict__ out)
{
    __shared__ __align__(16) __half Ks[3][64][40];   // [key][d]
    __shared__ __align__(16) __half Vt[3][32][72];   // [d][key]
    __shared__ float tbl[TBLN];

    const int b = blockIdx.z, h = blockIdx.y, q0 = blockIdx.x * 64;
    const int tid = threadIdx.x;
    const int warp = tid >> 5, lane = tid & 31;
    const int g = lane >> 2, t4 = lane & 3;
    const int wq = warp * 16;

    const float scale = 0.17677669529663687f;  // 1/sqrt(32)

    const int kkey = tid >> 2, kch = (tid & 3) * 8;
    const int vd = tid >> 3, vch = (tid & 7) * 8;

    const __half* kbase = g_qkv + (size_t)(b * SEQ + kkey) * (3 * DIM)
                          + DIM + h * HD + kch;
    const __half* vbase = g_vt + ((size_t)(b * HEADS + h) * HD + vd) * SEQ + vch;
    const size_t kstep = (size_t)32 * (3 * DIM);
    const size_t vstep = (size_t)16 * SEQ;

    const int kb_off = ((lane & 7) + ((lane >> 4) & 1) * 8) * 40
                       + ((lane >> 3) & 1) * 8;
    const int vb_off = ((lane & 7) + ((lane >> 4) & 1) * 8) * 72
                       + ((lane >> 3) & 1) * 8;

    #pragma unroll
    for (int st = 0; st < 2; st++) {
        cp16(smem_u32(&Ks[st][kkey][kch]), kbase + (size_t)(st * 64) * (3 * DIM));
        cp16(smem_u32(&Ks[st][kkey + 32][kch]),
             kbase + (size_t)(st * 64) * (3 * DIM) + kstep);
        cp16(smem_u32(&Vt[st][vd][vch]), vbase + st * 64);
        cp16(smem_u32(&Vt[st][vd + 16][vch]), vbase + st * 64 + vstep);
        cp_commit();
    }

    {
        const float* tsrc = g_tblt + (size_t)h * TBLN;
        for (int i = tid; i < TBLN; i += 128) tbl[i] = tsrc[i];
    }

    uint32_t qf[2][4];
    {
        const __half* q0p = g_qkv + (size_t)(b * SEQ + q0 + wq + g) * (3 * DIM) + h * HD;
        const __half* q1p = q0p + 8 * (3 * DIM);
        #pragma unroll
        for (int ks = 0; ks < 2; ks++) {
            const int kc = 16 * ks + 2 * t4;
            qf[ks][0] = *(const uint32_t*)(q0p + kc);
            qf[ks][1] = *(const uint32_t*)(q1p + kc);
            qf[ks][2] = *(const uint32_t*)(q0p + kc + 8);
            qf[ks][3] = *(const uint32_t*)(q1p + kc + 8);
        }
    }

    const int l0 = q0 + wq + g, l1 = l0 + 8;
    const int Cb0 = (l0 >> 5) * 63 + (l0 & 31) + 1984;
    const int Cb1 = (l1 >> 5) * 63 + (l1 & 31) + 1984;

    float m0 = -1e30f, m1 = -1e30f, li0 = 0.0f, li1 = 0.0f;
    float acc_o[4][4];
    #pragma unroll
    for (int ni = 0; ni < 4; ni++)
        #pragma unroll
        for (int c = 0; c < 4; c++) acc_o[ni][c] = 0.0f;

    for (int it = 0; it < NIT; it++) {
        const int s = it % 3;
        if (it + 1 < NIT) cp_wait<1>(); else cp_wait<0>();
        __syncthreads();
        if (it + 2 < NIT) {
            const int sn = (it + 2) % 3;
            const size_t ko = (size_t)((it + 2) * 64) * (3 * DIM);
            cp16(smem_u32(&Ks[sn][kkey][kch]), kbase + ko);
            cp16(smem_u32(&Ks[sn][kkey + 32][kch]), kbase + ko + kstep);
            cp16(smem_u32(&Vt[sn][vd][vch]), vbase + (it + 2) * 64);
            cp16(smem_u32(&Vt[sn][vd + 16][vch]), vbase + (it + 2) * 64 + vstep);
            cp_commit();
        }

        const uint32_t ksb = smem_u32(&Ks[s][0][0]);
        const uint32_t vsb = smem_u32(&Vt[s][0][0]);

        float sacc[8][4];
        #pragma unroll
        for (int ni = 0; ni < 8; ni++)
            #pragma unroll
            for (int c = 0; c < 4; c++) sacc[ni][c] = 0.0f;
        #pragma unroll
        for (int ks = 0; ks < 2; ks++) {
            uint32_t kb[8][2];
            #pragma unroll
            for (int nj = 0; nj < 4; nj++)
                ldsm4(kb[2 * nj][0], kb[2 * nj][1], kb[2 * nj + 1][0], kb[2 * nj + 1][1],
                      ksb + (uint32_t)(kb_off + nj * 16 * 40 + ks * 16) * 2);
            #pragma unroll
            for (int ni = 0; ni < 8; ni++)
                mma_f16(sacc[ni], qf[ks][0], qf[ks][1], qf[ks][2], qf[ks][3],
                        kb[ni][0], kb[ni][1]);
        }
        const int k0 = it * 64;
        {
            const int base0 = Cb0 - (k0 >> 5) * 63;
            const int base1 = Cb1 - (k0 >> 5) * 63;
            #pragma unroll
            for (int ni = 0; ni < 8; ni++) {
                const int off = (ni >> 2) * 63 + 8 * (ni & 3) + 2 * t4;
                sacc[ni][0] = fmaf(sacc[ni][0], scale, tbl[base0 - off]);
                sacc[ni][1] = fmaf(sacc[ni][1], scale, tbl[base0 - off - 1]);
                sacc[ni][2] = fmaf(sacc[ni][2], scale, tbl[base1 - off]);
                sacc[ni][3] = fmaf(sacc[ni][3], scale, tbl[base1 - off - 1]);
            }
        }

        float vmax0 = -1e30f, vmax1 = -1e30f;
        #pragma unroll
        for (int ni = 0; ni < 8; ni++) {
            vmax0 = fmaxf(vmax0, fmaxf(sacc[ni][0], sacc[ni][1]));
            vmax1 = fmaxf(vmax1, fmaxf(sacc[ni][2], sacc[ni][3]));
        }
        #pragma unroll
        for (int o = 1; o <= 2; o <<= 1) {
            vmax0 = fmaxf(vmax0, __shfl_xor_sync(0xffffffffu, vmax0, o));
            vmax1 = fmaxf(vmax1, __shfl_xor_sync(0xffffffffu, vmax1, o));
        }
        const float nm0 = fmaxf(m0, vmax0);
        const float nm1 = fmaxf(m1, vmax1);
        const float corr0 = __expf(m0 - nm0);
        const float corr1 = __expf(m1 - nm1);
        m0 = nm0; m1 = nm1;
        float rs0 = 0.0f, rs1 = 0.0f;

        uint32_t ph2[8][2];
        #pragma unroll
        for (int ni = 0; ni < 8; ni++) {
            const float p0 = __expf(sacc[ni][0] - m0);
            const float p1 = __expf(sacc[ni][1] - m0);
            const float p2 = __expf(sacc[ni][2] - m1);
            const float p3 = __expf(sacc[ni][3] - m1);
            rs0 += p0 + p1; rs1 += p2 + p3;
            ph2[ni][0] = pack_h2(p0, p1);
            ph2[ni][1] = pack_h2(p2, p3);
        }
        li0 = li0 * corr0 + rs0;
        li1 = li1 * corr1 + rs1;
        #pragma unroll
        for (int ni = 0; ni < 4; ni++) {
            acc_o[ni][0] *= corr0; acc_o[ni][1] *= corr0;
            acc_o[ni][2] *= corr1; acc_o[ni][3] *= corr1;
        }

        #pragma unroll
        for (int ks = 0; ks < 4; ks++) {
            uint32_t vb[4][2];
            #pragma unroll
            for (int nj = 0; nj < 2; nj++)
                ldsm4(vb[2 * nj][0], vb[2 * nj][1], vb[2 * nj + 1][0], vb[2 * nj + 1][1],
                      vsb + (uint32_t)(vb_off + nj * 16 * 72 + ks * 16) * 2);
            const uint32_t a0 = ph2[2 * ks][0];
            const uint32_t a1 = ph2[2 * ks][1];
            const uint32_t a2 = ph2[2 * ks + 1][0];
            const uint32_t a3 = ph2[2 * ks + 1][1];
            #pragma unroll
            for (int ni = 0; ni < 4; ni++)
                mma_f16(acc_o[ni], a0, a1, a2, a3, vb[ni][0], vb[ni][1]);
        }
    }

    #pragma unroll
    for (int o = 1; o <= 2; o <<= 1) {
        li0 += __shfl_xor_sync(0xffffffffu, li0, o);
        li1 += __shfl_xor_sync(0xffffffffu, li1, o);
    }
    const float inv0 = 1.0f / li0;
    const float inv1 = 1.0f / li1;
    __half* o0p = out + (size_t)(b * SEQ + q0 + wq + g) * DIM + h * HD;
    __half* o1p = o0p + 8 * DIM;
    #pragma unroll
    for (int ni = 0; ni < 4; ni++) {
        const int col = ni * 8 + t4 * 2;
        *(__half2*)(o0p + col) = __floats2half2_rn(acc_o[ni][0] * inv0,
                                                   acc_o[ni][1] * inv0);
        *(__half2*)(o1p + col) = __floats2half2_rn(acc_o[ni][2] * inv1,
                                                   acc_o[ni][3] * inv1);
    }
}

// ---------------- launch -----------------------------------------------------
extern "C" void kernel_launch(void* const* d_in, const int* in_sizes, int n_in,
                              void* d_out, int out_size)
{
    const float* x      = (const float*)d_in[0];
    const float* table  = (const float*)d_in[2];
    const float* qkv_w  = (const float*)d_in[3];
    const float* qkv_b  = (const float*)d_in[4];
    const float* proj_w = (const float*)d_in[5];
    const float* proj_b = (const float*)d_in[6];
    const float* n1_g   = (const float*)d_in[7];
    const float* n1_b   = (const float*)d_in[8];
    const float* n2_g   = (const float*)d_in[9];
    const float* n2_b   = (const float*)d_in[10];
    const float* fc1_w  = (const float*)d_in[11];
    const float* fc1_b  = (const float*)d_in[12];
    const float* fc2_w  = (const float*)d_in[13];
    const float* fc2_b  = (const float*)d_in[14];
    float* out = (float*)d_out;

    __half *h, *qkv, *attnout, *mlp1, *w;
    float *xres;
    cudaGetSymbolAddress((void**)&h,       g_h);
    cudaGetSymbolAddress((void**)&qkv,     g_qkv);
    cudaGetSymbolAddress((void**)&attnout, g_attnout);
    cudaGetSymbolAddress((void**)&xres,    g_xres);
    cudaGetSymbolAddress((void**)&mlp1,    g_mlp1);
    cudaGetSymbolAddress((void**)&w,       g_w);

    dim3 tb(32, 8);
    cvt_all_kernel<<<3072, tb>>>(qkv_w, proj_w, fc1_w, fc2_w, w);
    tblt_kernel<<<(TBLN + 255) / 256, 256>>>(table);
    ln_kernel<<<MROWS, 128>>>(x, n1_g, n1_b, h);
    gemm_h<EPI_BIAS, 1><<<dim3(12, 64), 128>>>(h, w + W_QKV, qkv_b, nullptr,
                                               nullptr, qkv, MROWS, 3 * DIM, DIM);
    vt_kernel<<<dim3(SEQ / 32, HEADS, BATCH), tb>>>();
    attn_h_kernel<<<dim3(SEQ / 64, HEADS, BATCH), 128>>>(attnout);
    gemm_h<EPI_RES, 0><<<dim3(4, 64), 128>>>(attnout, w + W_PROJ, proj_b, x,
                                             xres, nullptr, MROWS, DIM, DIM);
    ln_kernel<<<MROWS, 128>>>(xres, n2_g, n2_b, h);
    gemm_h<EPI_GELU, 1><<<dim3(16, 64), 128>>>(h, w + W_FC1, fc1_b, nullptr,
                                               nullptr, mlp1, MROWS, MLPH, DIM);
    gemm_h<EPI_RES, 0><<<dim3(4, 64), 128>>>(mlp1, w + W_FC2, fc2_b, xres,
                                             out, nullptr, MROWS, DIM, MLPH);
}